// round 7
// baseline (speedup 1.0000x reference)
#include <cuda_runtime.h>
#include <cstdint>

#define BHN   48
#define SEQ   1024
#define HD    64
#define TK    64
#define NQT   16          // SEQ / 64
#define NTHREADS 128
#define LAM   0.01f
#define EPSV  1e-6f
#define CLV   20.0f
#define SCALE 0.125f

#define STR   68          // row stride (floats) for all smem tiles
// smem: qT[64][68] | Sw[64][68] | Kb[64][68] | Vb[64][68]
#define SW_OFF  (64 * STR)
#define KB_OFF  (2 * 64 * STR)
#define VB_OFF  (3 * 64 * STR)
#define SMEM_FLOATS (4 * 64 * STR)

typedef unsigned long long u64;

__device__ __forceinline__ u64 pk2(float lo, float hi) {
    u64 r; asm("mov.b64 %0, {%1,%2};" : "=l"(r) : "f"(lo), "f"(hi)); return r;
}
__device__ __forceinline__ void unpk2(u64 v, float& lo, float& hi) {
    asm("mov.b64 {%0,%1}, %2;" : "=f"(lo), "=f"(hi) : "l"(v));
}
__device__ __forceinline__ void fma2(u64& d, u64 a, u64 b) {
    asm("fma.rn.f32x2 %0, %1, %2, %0;" : "+l"(d) : "l"(a), "l"(b));
}
__device__ __forceinline__ u64 mul2(u64 a, u64 b) {
    u64 r; asm("mul.rn.f32x2 %0, %1, %2;" : "=l"(r) : "l"(a), "l"(b)); return r;
}
__device__ __forceinline__ float sigm(float lg) {
    return __fdividef(1.f, 1.f + __expf(-lg));
}

__global__ void __launch_bounds__(NTHREADS, 3)
rse_attn(const float* __restrict__ gq, const float* __restrict__ gk,
         const float* __restrict__ gv, const float* __restrict__ gcos,
         const float* __restrict__ gsin, float* __restrict__ gout)
{
    extern __shared__ float smem[];
    float* qT = smem;            // [d][q]  RoPE'd Q transposed
    float* Sw = smem + SW_OFF;   // [k][q]  beta then w
    float* Kb = smem + KB_OFF;   // [k][d]  RoPE'd K tile
    float* Vb = smem + VB_OFF;   // [k][d]  V tile

    const int tid = threadIdx.x;
    const int idx = blockIdx.x;
    const int qt  = (NQT - 1) - (idx / BHN);   // heavy q-tiles first
    const int bh  = idx % BHN;
    const int q0  = qt * TK;
    const size_t base = (size_t)bh * SEQ * HD;

    const int lrow  = tid & 63;
    const int lhalf = tid >> 6;
    const int qg = tid & 15;      // 4-query group
    const int kg = tid >> 4;      // 8-key group / 8-dim group
    const int dg = kg;

    // ---- one-time: load Q, RoPE, store transposed qT[d][q] ----
    {
        const float* src = gq + base + (size_t)(q0 + lrow) * HD + lhalf * 32;
        const float* cc  = gcos + (q0 + lrow) * 32 + lhalf * 16;
        const float* ss  = gsin + (q0 + lrow) * 32 + lhalf * 16;
        #pragma unroll
        for (int j = 0; j < 8; j++) {
            float4 x = *(const float4*)(src + 4 * j);
            float2 c = *(const float2*)(cc + 2 * j);
            float2 s = *(const float2*)(ss + 2 * j);
            int d = lhalf * 32 + 4 * j;
            qT[(d + 0) * STR + lrow] = x.x * c.x - x.y * s.x;
            qT[(d + 1) * STR + lrow] = x.y * c.x + x.x * s.x;
            qT[(d + 2) * STR + lrow] = x.z * c.y - x.w * s.y;
            qT[(d + 3) * STR + lrow] = x.w * c.y + x.z * s.y;
        }
    }

    // ---- prologue: load K(0), RoPE, into Kb ----
    {
        const float* src = gk + base + (size_t)lrow * HD + lhalf * 32;
        const float* cc  = gcos + lrow * 32 + lhalf * 16;
        const float* ss  = gsin + lrow * 32 + lhalf * 16;
        float* dst = Kb + lrow * STR + lhalf * 32;
        #pragma unroll
        for (int j = 0; j < 8; j++) {
            float4 x = *(const float4*)(src + 4 * j);
            float2 c = *(const float2*)(cc + 2 * j);
            float2 s = *(const float2*)(ss + 2 * j);
            float4 kr;
            kr.x = x.x * c.x - x.y * s.x;
            kr.y = x.y * c.x + x.x * s.x;
            kr.z = x.z * c.y - x.w * s.y;
            kr.w = x.w * c.y + x.z * s.y;
            *(float4*)(dst + 4 * j) = kr;
        }
    }

    u64 acc3[4][4];
    #pragma unroll
    for (int j = 0; j < 4; j++)
        #pragma unroll
        for (int i = 0; i < 4; i++) acc3[j][i] = 0ull;
    float rem = 1.f, ws = 0.f;

    for (int h = 0; h <= qt; h++) {
        const int k0 = h * TK;
        // top barrier: P3(h-1) done with Vb/Sw; K(h) resident in Kb; qT ready
        __syncthreads();

        // ---- region A: V(h) global load (latency hidden by P1) ----
        {
            const float* src = gv + base + (size_t)(k0 + lrow) * HD + lhalf * 32;
            float* dst = Vb + lrow * STR + lhalf * 32;
            #pragma unroll
            for (int j = 0; j < 8; j++)
                *(float4*)(dst + 4 * j) = *(const float4*)(src + 4 * j);
        }
        // ---- region A: P1(h): S[8k x 4q] = K·Qᵀ, fused beta -> Sw ----
        {
            u64 a[8][2];
            #pragma unroll
            for (int i = 0; i < 8; i++) { a[i][0] = 0ull; a[i][1] = 0ull; }
            const float* kb = Kb + (kg * 8) * STR;
            const float* qb = qT + qg * 4;

            #pragma unroll 4
            for (int ds = 0; ds < 16; ds++) {
                u64 qq[4][2];
                #pragma unroll
                for (int j = 0; j < 4; j++) {
                    float4 qv = *(const float4*)(qb + (4 * ds + j) * STR);
                    qq[j][0] = pk2(qv.x, qv.y);
                    qq[j][1] = pk2(qv.z, qv.w);
                }
                #pragma unroll
                for (int i = 0; i < 8; i++) {
                    float4 kv = *(const float4*)(kb + i * STR + ds * 4);
                    u64 s0 = pk2(kv.x, kv.x);
                    fma2(a[i][0], s0, qq[0][0]); fma2(a[i][1], s0, qq[0][1]);
                    u64 s1 = pk2(kv.y, kv.y);
                    fma2(a[i][0], s1, qq[1][0]); fma2(a[i][1], s1, qq[1][1]);
                    u64 s2 = pk2(kv.z, kv.z);
                    fma2(a[i][0], s2, qq[2][0]); fma2(a[i][1], s2, qq[2][1]);
                    u64 s3 = pk2(kv.w, kv.w);
                    fma2(a[i][0], s3, qq[3][0]); fma2(a[i][1], s3, qq[3][1]);
                }
            }
            const float fkq = (float)(k0 + kg * 8 - q0 - qg * 4);  // (k - q) at i=0,j=0
            #pragma unroll
            for (int i = 0; i < 8; i++) {
                float d0, d1, d2, d3;
                unpk2(a[i][0], d0, d1);
                unpk2(a[i][1], d2, d3);
                const float pd = (fkq + (float)i) * LAM;
                float4 bo;
                bo.x = sigm(fminf(fmaxf(fmaf(d0, SCALE, pd            ), -CLV), CLV));
                bo.y = sigm(fminf(fmaxf(fmaf(d1, SCALE, pd - LAM      ), -CLV), CLV));
                bo.z = sigm(fminf(fmaxf(fmaf(d2, SCALE, pd - 2.f * LAM), -CLV), CLV));
                bo.w = sigm(fminf(fmaxf(fmaf(d3, SCALE, pd - 3.f * LAM), -CLV), CLV));
                *(float4*)(Sw + (kg * 8 + i) * STR + qg * 4) = bo;
            }
        }
        __syncthreads();

        // ---- region B: K(h+1) prefetch (all threads) + serial scan (64) ----
        if (h < qt) {
            const int kn = k0 + TK;
            const float* src = gk + base + (size_t)(kn + lrow) * HD + lhalf * 32;
            const float* cc  = gcos + (kn + lrow) * 32 + lhalf * 16;
            const float* ss  = gsin + (kn + lrow) * 32 + lhalf * 16;
            float* dst = Kb + lrow * STR + lhalf * 32;
            #pragma unroll
            for (int j = 0; j < 8; j++) {
                float4 x = *(const float4*)(src + 4 * j);
                float2 c = *(const float2*)(cc + 2 * j);
                float2 s = *(const float2*)(ss + 2 * j);
                float4 kr;
                kr.x = x.x * c.x - x.y * s.x;
                kr.y = x.y * c.x + x.x * s.x;
                kr.z = x.z * c.y - x.w * s.y;
                kr.w = x.w * c.y + x.z * s.y;
                *(float4*)(dst + 4 * j) = kr;
            }
        }
        if (tid < 64) {
            if (h < qt) {           // full chunk: mask-free scan
                #pragma unroll 1
                for (int g = 0; g < 8; g++) {
                    float b[8];
                    #pragma unroll
                    for (int j = 0; j < 8; j++)
                        b[j] = Sw[(g * 8 + j) * STR + lrow];
                    #pragma unroll
                    for (int j = 0; j < 8; j++) {
                        float w = b[j] * rem;
                        rem = fmaf(-w, rem, rem);
                        ws += w;
                        b[j] = w;
                    }
                    rem = fmaxf(rem, EPSV);
                    #pragma unroll
                    for (int j = 0; j < 8; j++)
                        Sw[(g * 8 + j) * STR + lrow] = b[j];
                }
            } else {                // diagonal chunk: causal mask
                const int nvalid = lrow + 1;
                #pragma unroll 1
                for (int g = 0; g < 8; g++) {
                    float b[8];
                    #pragma unroll
                    for (int j = 0; j < 8; j++)
                        b[j] = Sw[(g * 8 + j) * STR + lrow];
                    #pragma unroll
                    for (int j = 0; j < 8; j++) {
                        float w = (g * 8 + j < nvalid) ? b[j] * rem : 0.f;
                        rem = fmaf(-w, rem, rem);
                        ws += w;
                        b[j] = w;
                    }
                    rem = fmaxf(rem, EPSV);
                    #pragma unroll
                    for (int j = 0; j < 8; j++)
                        Sw[(g * 8 + j) * STR + lrow] = b[j];
                }
            }
        }
        __syncthreads();

        // ---- region C: P3(h): O[4q x 8d] += Wᵀ·V ----
        {
            const float* wb = Sw + qg * 4;
            const float* vb = Vb + dg * 8;
            #pragma unroll 4
            for (int k = 0; k < TK; k++) {
                float4 w = *(const float4*)(wb + k * STR);
                ulonglong2 va = *(const ulonglong2*)(vb + k * STR);
                ulonglong2 vc = *(const ulonglong2*)(vb + k * STR + 4);
                u64 s;
                s = pk2(w.x, w.x);
                fma2(acc3[0][0], s, va.x); fma2(acc3[0][1], s, va.y);
                fma2(acc3[0][2], s, vc.x); fma2(acc3[0][3], s, vc.y);
                s = pk2(w.y, w.y);
                fma2(acc3[1][0], s, va.x); fma2(acc3[1][1], s, va.y);
                fma2(acc3[1][2], s, vc.x); fma2(acc3[1][3], s, vc.y);
                s = pk2(w.z, w.z);
                fma2(acc3[2][0], s, va.x); fma2(acc3[2][1], s, va.y);
                fma2(acc3[2][2], s, vc.x); fma2(acc3[2][3], s, vc.y);
                s = pk2(w.w, w.w);
                fma2(acc3[3][0], s, va.x); fma2(acc3[3][1], s, va.y);
                fma2(acc3[3][2], s, vc.x); fma2(acc3[3][3], s, vc.y);
            }
        }
    }

    // ---- epilogue: share wsum via qT row 0, normalize, write out ----
    __syncthreads();
    if (tid < 64) qT[lrow] = ws;
    __syncthreads();
    float4 wsv = *(const float4*)(qT + qg * 4);
    float inv[4];
    inv[0] = __fdividef(1.f, fmaxf(wsv.x, EPSV));
    inv[1] = __fdividef(1.f, fmaxf(wsv.y, EPSV));
    inv[2] = __fdividef(1.f, fmaxf(wsv.z, EPSV));
    inv[3] = __fdividef(1.f, fmaxf(wsv.w, EPSV));
    #pragma unroll
    for (int j = 0; j < 4; j++) {
        u64 iv = pk2(inv[j], inv[j]);
        float* dst = gout + base + (size_t)(q0 + qg * 4 + j) * HD + dg * 8;
        ulonglong2 o;
        o.x = mul2(acc3[j][0], iv);
        o.y = mul2(acc3[j][1], iv);
        *(ulonglong2*)(dst) = o;
        o.x = mul2(acc3[j][2], iv);
        o.y = mul2(acc3[j][3], iv);
        *(ulonglong2*)(dst + 4) = o;
    }
}

extern "C" void kernel_launch(void* const* d_in, const int* in_sizes, int n_in,
                              void* d_out, int out_size)
{
    (void)in_sizes; (void)n_in; (void)out_size;
    const float* q    = (const float*)d_in[0];
    const float* k    = (const float*)d_in[1];
    const float* v    = (const float*)d_in[2];
    const float* cosc = (const float*)d_in[3];
    const float* sinc = (const float*)d_in[4];
    float* out = (float*)d_out;

    const int smem_bytes = SMEM_FLOATS * (int)sizeof(float);  // 69,632 B
    cudaFuncSetAttribute(rse_attn, cudaFuncAttributeMaxDynamicSharedMemorySize,
                         smem_bytes);
    rse_attn<<<NQT * BHN, NTHREADS, smem_bytes>>>(q, k, v, cosc, sinc, out);
}

// round 8
// speedup vs baseline: 1.1668x; 1.1668x over previous
#include <cuda_runtime.h>
#include <cstdint>

#define BHN   48
#define SEQ   1024
#define HD    64
#define TQ    128
#define TK    64
#define NQT   8           // SEQ / TQ
#define NTHREADS 128
#define LAM   0.01f
#define EPSV  1e-6f
#define CLV   20.0f
#define SCALE 0.125f

#define STRQ  132         // qT / Sw row stride (floats)
#define STRK  68          // Kb / Vb row stride (floats)
// smem: qT[64][132] | Sw[64][132] | Kb[64][68] | Vb[64][68]
#define SW_OFF  (64 * STRQ)
#define KB_OFF  (2 * 64 * STRQ)
#define VB_OFF  (KB_OFF + 64 * STRK)
#define SMEM_FLOATS (KB_OFF + 2 * 64 * STRK)

typedef unsigned long long u64;

__device__ __forceinline__ u64 pk2(float lo, float hi) {
    u64 r; asm("mov.b64 %0, {%1,%2};" : "=l"(r) : "f"(lo), "f"(hi)); return r;
}
__device__ __forceinline__ void unpk2(u64 v, float& lo, float& hi) {
    asm("mov.b64 {%0,%1}, %2;" : "=f"(lo), "=f"(hi) : "l"(v));
}
__device__ __forceinline__ void fma2(u64& d, u64 a, u64 b) {
    asm("fma.rn.f32x2 %0, %1, %2, %0;" : "+l"(d) : "l"(a), "l"(b));
}
__device__ __forceinline__ u64 mul2(u64 a, u64 b) {
    u64 r; asm("mul.rn.f32x2 %0, %1, %2;" : "=l"(r) : "l"(a), "l"(b)); return r;
}
__device__ __forceinline__ float sigm(float lg) {
    return __fdividef(1.f, 1.f + __expf(-lg));
}

__global__ void __launch_bounds__(NTHREADS, 2)
rse_attn(const float* __restrict__ gq, const float* __restrict__ gk,
         const float* __restrict__ gv, const float* __restrict__ gcos,
         const float* __restrict__ gsin, float* __restrict__ gout)
{
    extern __shared__ float smem[];
    float* qT = smem;            // [d][q]  RoPE'd Q transposed, q = 0..127
    float* Sw = smem + SW_OFF;   // [k][q]  beta then w
    float* Kb = smem + KB_OFF;   // [k][d]  RoPE'd K tile
    float* Vb = smem + VB_OFF;   // [k][d]  V tile

    const int tid = threadIdx.x;
    const int idx = blockIdx.x;
    const int qt  = (NQT - 1) - (idx / BHN);   // heavy q-tiles first
    const int bh  = idx % BHN;
    const int q0  = qt * TQ;
    const size_t base = (size_t)bh * SEQ * HD;

    const int qg = tid & 15;      // 8-query group (P1, P3, epilogue)
    const int kg = tid >> 4;      // 8-key group (P1) / 8-dim group (P3)
    const int dg = kg;
    const int hrow  = tid >> 1;   // 0..63: K/V loader row
    const int hhalf = tid & 1;    // half-row (32 floats)

    // ---- one-time: load Q (one full row per thread), RoPE, store qT[d][q] ----
    {
        const float* src = gq + base + (size_t)(q0 + tid) * HD;
        const float* cc  = gcos + (q0 + tid) * 32;
        const float* ss  = gsin + (q0 + tid) * 32;
        #pragma unroll
        for (int j = 0; j < 16; j++) {
            float4 x = *(const float4*)(src + 4 * j);
            float2 c = *(const float2*)(cc + 2 * j);
            float2 s = *(const float2*)(ss + 2 * j);
            qT[(4*j + 0) * STRQ + tid] = x.x * c.x - x.y * s.x;
            qT[(4*j + 1) * STRQ + tid] = x.y * c.x + x.x * s.x;
            qT[(4*j + 2) * STRQ + tid] = x.z * c.y - x.w * s.y;
            qT[(4*j + 3) * STRQ + tid] = x.w * c.y + x.z * s.y;
        }
    }
    // ---- prologue: load K(0), RoPE, into Kb (half-row per thread) ----
    {
        const float* src = gk + base + (size_t)hrow * HD + hhalf * 32;
        const float* cc  = gcos + hrow * 32 + hhalf * 16;
        const float* ss  = gsin + hrow * 32 + hhalf * 16;
        float* dst = Kb + hrow * STRK + hhalf * 32;
        #pragma unroll
        for (int j = 0; j < 8; j++) {
            float4 x = *(const float4*)(src + 4 * j);
            float2 c = *(const float2*)(cc + 2 * j);
            float2 s = *(const float2*)(ss + 2 * j);
            float4 kr;
            kr.x = x.x * c.x - x.y * s.x;
            kr.y = x.y * c.x + x.x * s.x;
            kr.z = x.z * c.y - x.w * s.y;
            kr.w = x.w * c.y + x.z * s.y;
            *(float4*)(dst + 4 * j) = kr;
        }
    }

    u64 acc[8][4];                // P3: 8 queries x 8 dims (f32x2 pairs)
    #pragma unroll
    for (int j = 0; j < 8; j++)
        #pragma unroll
        for (int i = 0; i < 4; i++) acc[j][i] = 0ull;
    float rem = 1.f, ws = 0.f;

    const int nchunk = 2 * qt + 2;
    for (int h = 0; h < nchunk; h++) {
        const int k0 = h * TK;
        // top barrier: P3(h-1) done (Sw/Vb free); K(h) resident in Kb
        __syncthreads();

        // ---- region A: P1(h): S[8k x 8q] = K·Qᵀ, fused beta -> Sw ----
        {
            u64 a[8][4];
            #pragma unroll
            for (int i = 0; i < 8; i++)
                #pragma unroll
                for (int j = 0; j < 4; j++) a[i][j] = 0ull;
            const float* kb = Kb + (kg * 8) * STRK;
            const float* qb = qT + qg * 8;

            #pragma unroll 2
            for (int ds = 0; ds < 16; ds++) {
                float4 kv[8];
                #pragma unroll
                for (int i = 0; i < 8; i++)
                    kv[i] = *(const float4*)(kb + i * STRK + ds * 4);
                #pragma unroll
                for (int j = 0; j < 4; j++) {
                    const float* qr = qb + (4 * ds + j) * STRQ;
                    float4 qa = *(const float4*)(qr);
                    float4 qc = *(const float4*)(qr + 4);
                    u64 v0 = pk2(qa.x, qa.y);
                    u64 v1 = pk2(qa.z, qa.w);
                    u64 v2 = pk2(qc.x, qc.y);
                    u64 v3 = pk2(qc.z, qc.w);
                    #pragma unroll
                    for (int i = 0; i < 8; i++) {
                        float ks = ((const float*)&kv[i])[j];
                        u64 s = pk2(ks, ks);
                        fma2(a[i][0], s, v0);
                        fma2(a[i][1], s, v1);
                        fma2(a[i][2], s, v2);
                        fma2(a[i][3], s, v3);
                    }
                }
            }
            // fused: dot -> logit -> clamp -> beta
            const float fkq = (float)(k0 + kg * 8 - (q0 + qg * 8));
            #pragma unroll
            for (int i = 0; i < 8; i++) {
                float d0, d1, d2, d3, d4, d5, d6, d7;
                unpk2(a[i][0], d0, d1);
                unpk2(a[i][1], d2, d3);
                unpk2(a[i][2], d4, d5);
                unpk2(a[i][3], d6, d7);
                const float pd = (fkq + (float)i) * LAM;
                float4 b0, b1;
                b0.x = sigm(fminf(fmaxf(fmaf(d0, SCALE, pd            ), -CLV), CLV));
                b0.y = sigm(fminf(fmaxf(fmaf(d1, SCALE, pd - LAM      ), -CLV), CLV));
                b0.z = sigm(fminf(fmaxf(fmaf(d2, SCALE, pd - 2.f * LAM), -CLV), CLV));
                b0.w = sigm(fminf(fmaxf(fmaf(d3, SCALE, pd - 3.f * LAM), -CLV), CLV));
                b1.x = sigm(fminf(fmaxf(fmaf(d4, SCALE, pd - 4.f * LAM), -CLV), CLV));
                b1.y = sigm(fminf(fmaxf(fmaf(d5, SCALE, pd - 5.f * LAM), -CLV), CLV));
                b1.z = sigm(fminf(fmaxf(fmaf(d6, SCALE, pd - 6.f * LAM), -CLV), CLV));
                b1.w = sigm(fminf(fmaxf(fmaf(d7, SCALE, pd - 7.f * LAM), -CLV), CLV));
                float* sd = Sw + (kg * 8 + i) * STRQ + qg * 8;
                *(float4*)(sd)     = b0;
                *(float4*)(sd + 4) = b1;
            }
        }
        __syncthreads();

        // ---- region B: V(h) load + serial scan (all 128 threads scan) ----
        {
            const float* src = gv + base + (size_t)(k0 + hrow) * HD + hhalf * 32;
            float* dst = Vb + hrow * STRK + hhalf * 32;
            #pragma unroll
            for (int j = 0; j < 8; j++)
                *(float4*)(dst + 4 * j) = *(const float4*)(src + 4 * j);
        }
        if (h < 2 * qt) {          // full chunk for every query: mask-free
            #pragma unroll 1
            for (int g = 0; g < 8; g++) {
                float b[8];
                #pragma unroll
                for (int j = 0; j < 8; j++)
                    b[j] = Sw[(g * 8 + j) * STRQ + tid];
                #pragma unroll
                for (int j = 0; j < 8; j++) {
                    float w = b[j] * rem;
                    rem = fmaf(-w, rem, rem);
                    ws += w;
                    b[j] = w;
                }
                rem = fmaxf(rem, EPSV);
                #pragma unroll
                for (int j = 0; j < 8; j++)
                    Sw[(g * 8 + j) * STRQ + tid] = b[j];
            }
        } else {                   // diagonal chunks: causal mask
            const int nvalid = min(64, max(0, tid + 1 - (k0 - q0)));
            #pragma unroll 1
            for (int g = 0; g < 8; g++) {
                float b[8];
                #pragma unroll
                for (int j = 0; j < 8; j++)
                    b[j] = Sw[(g * 8 + j) * STRQ + tid];
                #pragma unroll
                for (int j = 0; j < 8; j++) {
                    float w = (g * 8 + j < nvalid) ? b[j] * rem : 0.f;
                    rem = fmaf(-w, rem, rem);
                    ws += w;
                    b[j] = w;
                }
                rem = fmaxf(rem, EPSV);
                #pragma unroll
                for (int j = 0; j < 8; j++)
                    Sw[(g * 8 + j) * STRQ + tid] = b[j];
            }
        }
        __syncthreads();

        // ---- region C: K(h+1) prefetch (latency drains under P3) + P3(h) ----
        if (h + 1 < nchunk) {
            const int kn = k0 + TK;
            const float* src = gk + base + (size_t)(kn + hrow) * HD + hhalf * 32;
            const float* cc  = gcos + (kn + hrow) * 32 + hhalf * 16;
            const float* ss  = gsin + (kn + hrow) * 32 + hhalf * 16;
            float* dst = Kb + hrow * STRK + hhalf * 32;
            #pragma unroll
            for (int j = 0; j < 8; j++) {
                float4 x = *(const float4*)(src + 4 * j);
                float2 c = *(const float2*)(cc + 2 * j);
                float2 s = *(const float2*)(ss + 2 * j);
                float4 kr;
                kr.x = x.x * c.x - x.y * s.x;
                kr.y = x.y * c.x + x.x * s.x;
                kr.z = x.z * c.y - x.w * s.y;
                kr.w = x.w * c.y + x.z * s.y;
                *(float4*)(dst + 4 * j) = kr;
            }
        }
        // P3(h): O[8q x 8d] += Wᵀ·V
        {
            const float* wb = Sw + qg * 8;
            const float* vb = Vb + dg * 8;
            #pragma unroll 2
            for (int k = 0; k < TK; k++) {
                float4 w0 = *(const float4*)(wb + k * STRQ);
                float4 w1 = *(const float4*)(wb + k * STRQ + 4);
                ulonglong2 va = *(const ulonglong2*)(vb + k * STRK);
                ulonglong2 vc = *(const ulonglong2*)(vb + k * STRK + 4);
                u64 s;
                s = pk2(w0.x, w0.x);
                fma2(acc[0][0], s, va.x); fma2(acc[0][1], s, va.y);
                fma2(acc[0][2], s, vc.x); fma2(acc[0][3], s, vc.y);
                s = pk2(w0.y, w0.y);
                fma2(acc[1][0], s, va.x); fma2(acc[1][1], s, va.y);
                fma2(acc[1][2], s, vc.x); fma2(acc[1][3], s, vc.y);
                s = pk2(w0.z, w0.z);
                fma2(acc[2][0], s, va.x); fma2(acc[2][1], s, va.y);
                fma2(acc[2][2], s, vc.x); fma2(acc[2][3], s, vc.y);
                s = pk2(w0.w, w0.w);
                fma2(acc[3][0], s, va.x); fma2(acc[3][1], s, va.y);
                fma2(acc[3][2], s, vc.x); fma2(acc[3][3], s, vc.y);
                s = pk2(w1.x, w1.x);
                fma2(acc[4][0], s, va.x); fma2(acc[4][1], s, va.y);
                fma2(acc[4][2], s, vc.x); fma2(acc[4][3], s, vc.y);
                s = pk2(w1.y, w1.y);
                fma2(acc[5][0], s, va.x); fma2(acc[5][1], s, va.y);
                fma2(acc[5][2], s, vc.x); fma2(acc[5][3], s, vc.y);
                s = pk2(w1.z, w1.z);
                fma2(acc[6][0], s, va.x); fma2(acc[6][1], s, va.y);
                fma2(acc[6][2], s, vc.x); fma2(acc[6][3], s, vc.y);
                s = pk2(w1.w, w1.w);
                fma2(acc[7][0], s, va.x); fma2(acc[7][1], s, va.y);
                fma2(acc[7][2], s, vc.x); fma2(acc[7][3], s, vc.y);
            }
        }
    }

    // ---- epilogue: share wsum via Sw row 0, normalize, write out ----
    __syncthreads();
    Sw[tid] = ws;
    __syncthreads();
    float4 s0 = *(const float4*)(Sw + qg * 8);
    float4 s1 = *(const float4*)(Sw + qg * 8 + 4);
    float inv[8];
    inv[0] = __fdividef(1.f, fmaxf(s0.x, EPSV));
    inv[1] = __fdividef(1.f, fmaxf(s0.y, EPSV));
    inv[2] = __fdividef(1.f, fmaxf(s0.z, EPSV));
    inv[3] = __fdividef(1.f, fmaxf(s0.w, EPSV));
    inv[4] = __fdividef(1.f, fmaxf(s1.x, EPSV));
    inv[5] = __fdividef(1.f, fmaxf(s1.y, EPSV));
    inv[6] = __fdividef(1.f, fmaxf(s1.z, EPSV));
    inv[7] = __fdividef(1.f, fmaxf(s1.w, EPSV));
    #pragma unroll
    for (int j = 0; j < 8; j++) {
        u64 iv = pk2(inv[j], inv[j]);
        float* dst = gout + base + (size_t)(q0 + qg * 8 + j) * HD + dg * 8;
        ulonglong2 o;
        o.x = mul2(acc[j][0], iv);
        o.y = mul2(acc[j][1], iv);
        *(ulonglong2*)(dst) = o;
        o.x = mul2(acc[j][2], iv);
        o.y = mul2(acc[j][3], iv);
        *(ulonglong2*)(dst + 4) = o;
    }
}

extern "C" void kernel_launch(void* const* d_in, const int* in_sizes, int n_in,
                              void* d_out, int out_size)
{
    (void)in_sizes; (void)n_in; (void)out_size;
    const float* q    = (const float*)d_in[0];
    const float* k    = (const float*)d_in[1];
    const float* v    = (const float*)d_in[2];
    const float* cosc = (const float*)d_in[3];
    const float* sinc = (const float*)d_in[4];
    float* out = (float*)d_out;

    const int smem_bytes = SMEM_FLOATS * (int)sizeof(float);  // 102,400 B
    cudaFuncSetAttribute(rse_attn, cudaFuncAttributeMaxDynamicSharedMemorySize,
                         smem_bytes);
    rse_attn<<<NQT * BHN, NTHREADS, smem_bytes>>>(q, k, v, cosc, sinc, out);
}

// round 11
// speedup vs baseline: 1.2314x; 1.0553x over previous
#include <cuda_runtime.h>
#include <cstdint>

#define BHN   48
#define SEQ   1024
#define HD    64
#define TQ    128
#define TK    64
#define NQT   8           // SEQ / TQ
#define NTHREADS 128
#define LAM   0.01f
#define EPSV  1e-6f
#define CLV   20.0f
#define SCALE 0.125f

#define STRQ  132         // qT / Sw row stride (floats)
#define STRK  68          // Kb / Vb row stride (floats)
#define SW_OFF  (64 * STRQ)
#define KB_OFF  (2 * 64 * STRQ)
#define VB_OFF  (KB_OFF + 64 * STRK)
#define SMEM_FLOATS (KB_OFF + 2 * 64 * STRK)

typedef unsigned long long u64;

__device__ __forceinline__ u64 pk2(float lo, float hi) {
    u64 r; asm("mov.b64 %0, {%1,%2};" : "=l"(r) : "f"(lo), "f"(hi)); return r;
}
__device__ __forceinline__ void unpk2(u64 v, float& lo, float& hi) {
    asm("mov.b64 {%0,%1}, %2;" : "=f"(lo), "=f"(hi) : "l"(v));
}
__device__ __forceinline__ void fma2(u64& d, u64 a, u64 b) {
    asm("fma.rn.f32x2 %0, %1, %2, %0;" : "+l"(d) : "l"(a), "l"(b));
}
__device__ __forceinline__ u64 mul2(u64 a, u64 b) {
    u64 r; asm("mul.rn.f32x2 %0, %1, %2;" : "=l"(r) : "l"(a), "l"(b)); return r;
}
// sigmoid(x) = 0.5*tanh(0.5x)+0.5 via single MUFU tanh.approx
__device__ __forceinline__ float sigm(float lg) {
    float t;
    asm("tanh.approx.f32 %0, %1;" : "=f"(t) : "f"(lg * 0.5f));
    return fmaf(t, 0.5f, 0.5f);
}

__global__ void __launch_bounds__(NTHREADS, 2)
rse_attn(const float* __restrict__ gq, const float* __restrict__ gk,
         const float* __restrict__ gv, const float* __restrict__ gcos,
         const float* __restrict__ gsin, float* __restrict__ gout)
{
    extern __shared__ float smem[];
    float* qT = smem;            // [d][q]  RoPE'd Q transposed, q = 0..127
    float* Sw = smem + SW_OFF;   // [k][q]  beta then w
    float* Kb = smem + KB_OFF;   // [k][d]  RoPE'd K tile
    float* Vb = smem + VB_OFF;   // [k][d]  V tile

    const int tid = threadIdx.x;
    const int idx = blockIdx.x;
    const int qt  = (NQT - 1) - (idx / BHN);   // heavy q-tiles first
    const int bh  = idx % BHN;
    const int q0  = qt * TQ;
    const size_t base = (size_t)bh * SEQ * HD;

    const int qg = tid & 15;      // 8-query group
    const int kg = tid >> 4;      // 8-key group (P1) / 8-dim group (P3)
    const int dg = kg;
    const int hrow  = tid >> 1;   // 0..63: loader row
    const int hhalf = tid & 1;

    // ---- one-time: load Q row, RoPE, store transposed qT[d][q] ----
    {
        const float* src = gq + base + (size_t)(q0 + tid) * HD;
        const float* cc  = gcos + (q0 + tid) * 32;
        const float* ss  = gsin + (q0 + tid) * 32;
        #pragma unroll
        for (int j = 0; j < 16; j++) {
            float4 x = *(const float4*)(src + 4 * j);
            float2 c = *(const float2*)(cc + 2 * j);
            float2 s = *(const float2*)(ss + 2 * j);
            qT[(4*j + 0) * STRQ + tid] = x.x * c.x - x.y * s.x;
            qT[(4*j + 1) * STRQ + tid] = x.y * c.x + x.x * s.x;
            qT[(4*j + 2) * STRQ + tid] = x.z * c.y - x.w * s.y;
            qT[(4*j + 3) * STRQ + tid] = x.w * c.y + x.z * s.y;
        }
    }
    // ---- prologue: load K(0), RoPE, into Kb ----
    {
        const float* src = gk + base + (size_t)hrow * HD + hhalf * 32;
        const float* cc  = gcos + hrow * 32 + hhalf * 16;
        const float* ss  = gsin + hrow * 32 + hhalf * 16;
        float* dst = Kb + hrow * STRK + hhalf * 32;
        #pragma unroll
        for (int j = 0; j < 8; j++) {
            float4 x = *(const float4*)(src + 4 * j);
            float2 c = *(const float2*)(cc + 2 * j);
            float2 s = *(const float2*)(ss + 2 * j);
            float4 kr;
            kr.x = x.x * c.x - x.y * s.x;
            kr.y = x.y * c.x + x.x * s.x;
            kr.z = x.z * c.y - x.w * s.y;
            kr.w = x.w * c.y + x.z * s.y;
            *(float4*)(dst + 4 * j) = kr;
        }
    }

    u64 acc[8][4];
    #pragma unroll
    for (int j = 0; j < 8; j++)
        #pragma unroll
        for (int i = 0; i < 4; i++) acc[j][i] = 0ull;
    float rem = 1.f, ws = 0.f;

    const int nchunk = 2 * qt + 2;
    for (int h = 0; h < nchunk; h++) {
        const int k0 = h * TK;
        // top barrier: P3(h-1) done (Sw/Vb free); K(h) resident in Kb
        __syncthreads();

        // ---- region A: P1(h): S[8k x 8q] = K·Qᵀ, fused beta -> Sw ----
        {
            u64 a[8][4];
            #pragma unroll
            for (int i = 0; i < 8; i++)
                #pragma unroll
                for (int j = 0; j < 4; j++) a[i][j] = 0ull;
            const float* kb = Kb + (kg * 8) * STRK;
            const float* qb = qT + qg * 8;

            #pragma unroll 2
            for (int ds = 0; ds < 16; ds++) {
                float4 kv[8];
                #pragma unroll
                for (int i = 0; i < 8; i++)
                    kv[i] = *(const float4*)(kb + i * STRK + ds * 4);
                #pragma unroll
                for (int j = 0; j < 4; j++) {
                    const float* qr = qb + (4 * ds + j) * STRQ;
                    float4 qa = *(const float4*)(qr);
                    float4 qc = *(const float4*)(qr + 4);
                    u64 v0 = pk2(qa.x, qa.y);
                    u64 v1 = pk2(qa.z, qa.w);
                    u64 v2 = pk2(qc.x, qc.y);
                    u64 v3 = pk2(qc.z, qc.w);
                    #pragma unroll
                    for (int i = 0; i < 8; i++) {
                        float ks = ((const float*)&kv[i])[j];
                        u64 s = pk2(ks, ks);
                        fma2(a[i][0], s, v0);
                        fma2(a[i][1], s, v1);
                        fma2(a[i][2], s, v2);
                        fma2(a[i][3], s, v3);
                    }
                }
            }
            const float fkq = (float)(k0 + kg * 8 - (q0 + qg * 8));
            #pragma unroll
            for (int i = 0; i < 8; i++) {
                float d0, d1, d2, d3, d4, d5, d6, d7;
                unpk2(a[i][0], d0, d1);
                unpk2(a[i][1], d2, d3);
                unpk2(a[i][2], d4, d5);
                unpk2(a[i][3], d6, d7);
                const float pd = (fkq + (float)i) * LAM;
                float4 b0, b1;
                b0.x = sigm(fminf(fmaxf(fmaf(d0, SCALE, pd            ), -CLV), CLV));
                b0.y = sigm(fminf(fmaxf(fmaf(d1, SCALE, pd - LAM      ), -CLV), CLV));
                b0.z = sigm(fminf(fmaxf(fmaf(d2, SCALE, pd - 2.f * LAM), -CLV), CLV));
                b0.w = sigm(fminf(fmaxf(fmaf(d3, SCALE, pd - 3.f * LAM), -CLV), CLV));
                b1.x = sigm(fminf(fmaxf(fmaf(d4, SCALE, pd - 4.f * LAM), -CLV), CLV));
                b1.y = sigm(fminf(fmaxf(fmaf(d5, SCALE, pd - 5.f * LAM), -CLV), CLV));
                b1.z = sigm(fminf(fmaxf(fmaf(d6, SCALE, pd - 6.f * LAM), -CLV), CLV));
                b1.w = sigm(fminf(fmaxf(fmaf(d7, SCALE, pd - 7.f * LAM), -CLV), CLV));
                float* sd = Sw + (kg * 8 + i) * STRQ + qg * 8;
                *(float4*)(sd)     = b0;
                *(float4*)(sd + 4) = b1;
            }
        }
        __syncthreads();

        // ---- region B: V LDGs (drain under scan) + scan + V store ----
        float4 vreg[8];
        {
            const float* src = gv + base + (size_t)(k0 + hrow) * HD + hhalf * 32;
            #pragma unroll
            for (int j = 0; j < 8; j++)
                vreg[j] = *(const float4*)(src + 4 * j);
        }
        if (h < 2 * qt) {          // full chunk: mask-free
            #pragma unroll 1
            for (int g = 0; g < 8; g++) {
                float b[8];
                #pragma unroll
                for (int j = 0; j < 8; j++)
                    b[j] = Sw[(g * 8 + j) * STRQ + tid];
                #pragma unroll
                for (int j = 0; j < 8; j++) {
                    float w = b[j] * rem;
                    rem = fmaf(-w, rem, rem);
                    ws += w;
                    b[j] = w;
                }
                rem = fmaxf(rem, EPSV);
                #pragma unroll
                for (int j = 0; j < 8; j++)
                    Sw[(g * 8 + j) * STRQ + tid] = b[j];
            }
        } else {                   // diagonal chunks: causal mask
            const int nvalid = min(64, max(0, tid + 1 - (k0 - q0)));
            #pragma unroll 1
            for (int g = 0; g < 8; g++) {
                float b[8];
                #pragma unroll
                for (int j = 0; j < 8; j++)
                    b[j] = Sw[(g * 8 + j) * STRQ + tid];
                #pragma unroll
                for (int j = 0; j < 8; j++) {
                    float w = (g * 8 + j < nvalid) ? b[j] * rem : 0.f;
                    rem = fmaf(-w, rem, rem);
                    ws += w;
                    b[j] = w;
                }
                rem = fmaxf(rem, EPSV);
                #pragma unroll
                for (int j = 0; j < 8; j++)
                    Sw[(g * 8 + j) * STRQ + tid] = b[j];
            }
        }
        {
            float* dst = Vb + hrow * STRK + hhalf * 32;
            #pragma unroll
            for (int j = 0; j < 8; j++)
                *(float4*)(dst + 4 * j) = vreg[j];
        }
        __syncthreads();

        // ---- region C: raw-K(h+1) LDGs (drain under P3) + P3 + RoPE+store ----
        float4 kreg[8];
        const bool pf = (h + 1 < nchunk);
        if (pf) {
            const float* src = gk + base + (size_t)(k0 + TK + hrow) * HD + hhalf * 32;
            #pragma unroll
            for (int j = 0; j < 8; j++)
                kreg[j] = *(const float4*)(src + 4 * j);
        }
        {
            const float* wb = Sw + qg * 8;
            const float* vb = Vb + dg * 8;
            #pragma unroll 2
            for (int k = 0; k < TK; k++) {
                float4 w0 = *(const float4*)(wb + k * STRQ);
                float4 w1 = *(const float4*)(wb + k * STRQ + 4);
                ulonglong2 va = *(const ulonglong2*)(vb + k * STRK);
                ulonglong2 vc = *(const ulonglong2*)(vb + k * STRK + 4);
                u64 s;
                s = pk2(w0.x, w0.x);
                fma2(acc[0][0], s, va.x); fma2(acc[0][1], s, va.y);
                fma2(acc[0][2], s, vc.x); fma2(acc[0][3], s, vc.y);
                s = pk2(w0.y, w0.y);
                fma2(acc[1][0], s, va.x); fma2(acc[1][1], s, va.y);
                fma2(acc[1][2], s, vc.x); fma2(acc[1][3], s, vc.y);
                s = pk2(w0.z, w0.z);
                fma2(acc[2][0], s, va.x); fma2(acc[2][1], s, va.y);
                fma2(acc[2][2], s, vc.x); fma2(acc[2][3], s, vc.y);
                s = pk2(w0.w, w0.w);
                fma2(acc[3][0], s, va.x); fma2(acc[3][1], s, va.y);
                fma2(acc[3][2], s, vc.x); fma2(acc[3][3], s, vc.y);
                s = pk2(w1.x, w1.x);
                fma2(acc[4][0], s, va.x); fma2(acc[4][1], s, va.y);
                fma2(acc[4][2], s, vc.x); fma2(acc[4][3], s, vc.y);
                s = pk2(w1.y, w1.y);
                fma2(acc[5][0], s, va.x); fma2(acc[5][1], s, va.y);
                fma2(acc[5][2], s, vc.x); fma2(acc[5][3], s, vc.y);
                s = pk2(w1.z, w1.z);
                fma2(acc[6][0], s, va.x); fma2(acc[6][1], s, va.y);
                fma2(acc[6][2], s, vc.x); fma2(acc[6][3], s, vc.y);
                s = pk2(w1.w, w1.w);
                fma2(acc[7][0], s, va.x); fma2(acc[7][1], s, va.y);
                fma2(acc[7][2], s, vc.x); fma2(acc[7][3], s, vc.y);
            }
        }
        if (pf) {
            // cos/sin loaded here (L2-hot, ~230cyc once) then RoPE + store
            const int kn = k0 + TK + hrow;
            const float* cc = gcos + kn * 32 + hhalf * 16;
            const float* ss = gsin + kn * 32 + hhalf * 16;
            float* dst = Kb + hrow * STRK + hhalf * 32;
            #pragma unroll
            for (int j = 0; j < 8; j++) {
                float2 c = *(const float2*)(cc + 2 * j);
                float2 s = *(const float2*)(ss + 2 * j);
                float4 x = kreg[j];
                float4 kr;
                kr.x = x.x * c.x - x.y * s.x;
                kr.y = x.y * c.x + x.x * s.x;
                kr.z = x.z * c.y - x.w * s.y;
                kr.w = x.w * c.y + x.z * s.y;
                *(float4*)(dst + 4 * j) = kr;
            }
        }
    }

    // ---- epilogue: share wsum via Sw row 0, normalize, write out ----
    __syncthreads();
    Sw[tid] = ws;
    __syncthreads();
    float4 s0 = *(const float4*)(Sw + qg * 8);
    float4 s1 = *(const float4*)(Sw + qg * 8 + 4);
    float inv[8];
    inv[0] = __fdividef(1.f, fmaxf(s0.x, EPSV));
    inv[1] = __fdividef(1.f, fmaxf(s0.y, EPSV));
    inv[2] = __fdividef(1.f, fmaxf(s0.z, EPSV));
    inv[3] = __fdividef(1.f, fmaxf(s0.w, EPSV));
    inv[4] = __fdividef(1.f, fmaxf(s1.x, EPSV));
    inv[5] = __fdividef(1.f, fmaxf(s1.y, EPSV));
    inv[6] = __fdividef(1.f, fmaxf(s1.z, EPSV));
    inv[7] = __fdividef(1.f, fmaxf(s1.w, EPSV));
    #pragma unroll
    for (int j = 0; j < 8; j++) {
        u64 iv = pk2(inv[j], inv[j]);
        float* dst = gout + base + (size_t)(q0 + qg * 8 + j) * HD + dg * 8;
        ulonglong2 o;
        o.x = mul2(acc[j][0], iv);
        o.y = mul2(acc[j][1], iv);
        *(ulonglong2*)(dst) = o;
        o.x = mul2(acc[j][2], iv);
        o.y = mul2(acc[j][3], iv);
        *(ulonglong2*)(dst + 4) = o;
    }
}

extern "C" void kernel_launch(void* const* d_in, const int* in_sizes, int n_in,
                              void* d_out, int out_size)
{
    (void)in_sizes; (void)n_in; (void)out_size;
    const float* q    = (const float*)d_in[0];
    const float* k    = (const float*)d_in[1];
    const float* v    = (const float*)d_in[2];
    const float* cosc = (const float*)d_in[3];
    const float* sinc = (const float*)d_in[4];
    float* out = (float*)d_out;

    const int smem_bytes = SMEM_FLOATS * (int)sizeof(float);  // 102,400 B
    cudaFuncSetAttribute(rse_attn, cudaFuncAttributeMaxDynamicSharedMemorySize,
                         smem_bytes);
    rse_attn<<<NQT * BHN, NTHREADS, smem_bytes>>>(q, k, v, cosc, sinc, out);
}